// round 6
// baseline (speedup 1.0000x reference)
#include <cuda_runtime.h>

#define IMG_W 512
#define IMG_H 512
#define PLANE (IMG_W * IMG_H)
#define RPT   16
#define STRIPS_PER_PLANE (IMG_H / RPT)   // 32

__device__ __forceinline__ float med3f(float a, float b, float c) {
    return fmaxf(fminf(a, b), fminf(fmaxf(a, b), c));
}

struct RawRow {            // 4 values: halo-left, c0, c1, halo-right
    float2 v;
    float l, r;
};

struct SortedRow {         // sorted vertical inputs for 2 columns
    float lo0, lo1;
    float mi0, mi1;
    float hi0, hi1;
};

// Aligned float2 + two independent scalar halo loads (L1 hits from neighbors).
__device__ __forceinline__ RawRow load_raw(const float* __restrict__ ip,
                                           int y, int x0, int xl, int xr) {
    const float* __restrict__ rp = ip + y * IMG_W;
    RawRow o;
    o.v = *(const float2*)(rp + x0);
    o.l = rp[xl];
    o.r = rp[xr];
    return o;
}

__device__ __forceinline__ SortedRow sort_row(const RawRow& rr) {
    float s0 = rr.l, s1 = rr.v.x, s2 = rr.v.y, s3 = rr.r;
    SortedRow o;
    #define SORT3(a_, b_, c_, LO, MI, HI) {            \
        float a = (a_), b = (b_), c = (c_), t;          \
        t = fminf(a, b); b = fmaxf(a, b); a = t;        \
        t = fminf(b, c); c = fmaxf(b, c); b = t;        \
        t = fminf(a, b); b = fmaxf(a, b); a = t;        \
        o.LO = a; o.MI = b; o.HI = c; }
    SORT3(s0, s1, s2, lo0, mi0, hi0);
    SORT3(s1, s2, s3, lo1, mi1, hi1);
    #undef SORT3
    return o;
}

__device__ __forceinline__ float tail(float lA, float lB, float lC,
                                      float mA, float mB, float mC,
                                      float hA, float hB, float hC) {
    float mx = fmaxf(fmaxf(lA, lB), lC);   // max of mins
    float mn = fminf(fminf(hA, hB), hC);   // min of maxes
    float md = med3f(mA, mB, mC);          // med of mids
    return med3f(mx, md, mn);
}

__global__ __launch_bounds__(128)
void MedianFilter2D_68745246540291_kernel(const float* __restrict__ in,
                                          float* __restrict__ out) {
    const int t = threadIdx.x;                   // 0..127 -> 2 columns each
    const int b = blockIdx.x;

    const int half  = b & 1;                     // which 256-col half of the row
    const int sy    = (b >> 1) & (STRIPS_PER_PLANE - 1);
    const int plane = b >> 6;                    // / (2*STRIPS_PER_PLANE)

    const int y0 = sy * RPT;
    const int x0 = (half * 128 + t) * 2;

    const float* __restrict__ ip = in  + (size_t)plane * PLANE;
    float*       __restrict__ op = out + (size_t)plane * PLANE;

    // Loop-invariant halo columns (image-edge reflect folded in)
    const int xl = (x0 == 0)           ? 1         : x0 - 1;
    const int xr = (x0 + 2 >= IMG_W)   ? IMG_W - 2 : x0 + 2;

    // Vertical reflect resolved once per block
    const int ytop = (sy == 0)                    ? 1         : y0 - 1;
    const int ybot = (sy == STRIPS_PER_PLANE - 1) ? IMG_H - 2 : y0 + RPT;

    SortedRow A = sort_row(load_raw(ip, ytop, x0, xl, xr));
    SortedRow B = sort_row(load_raw(ip, y0,   x0, xl, xr));
    RawRow nxt  = load_raw(ip, y0 + 1, x0, xl, xr);

    #pragma unroll
    for (int i = 0; i < RPT; i++) {
        RawRow cur = nxt;
        if (i + 1 < RPT) {
            const int yn = (i + 2 == RPT) ? ybot : (y0 + i + 2);
            nxt = load_raw(ip, yn, x0, xl, xr);
        }

        SortedRow C = sort_row(cur);

        float2 res;
        res.x = tail(A.lo0, B.lo0, C.lo0, A.mi0, B.mi0, C.mi0, A.hi0, B.hi0, C.hi0);
        res.y = tail(A.lo1, B.lo1, C.lo1, A.mi1, B.mi1, C.mi1, A.hi1, B.hi1, C.hi1);

        *(float2*)(op + (size_t)(y0 + i) * IMG_W + x0) = res;

        A = B; B = C;   // register renaming under full unroll
    }
}

extern "C" void kernel_launch(void* const* d_in, const int* in_sizes, int n_in,
                              void* d_out, int out_size) {
    const float* image = (const float*)d_in[0];
    float* out = (float*)d_out;

    // 48 planes * 32 strips(16 rows) * 2 half-rows = 3072 blocks of 128 threads
    dim3 block(128, 1, 1);
    dim3 grid(48 * STRIPS_PER_PLANE * 2, 1, 1);
    MedianFilter2D_68745246540291_kernel<<<grid, block>>>(image, out);
}

// round 7
// speedup vs baseline: 1.0954x; 1.0954x over previous
#include <cuda_runtime.h>

#define IMG_W 512
#define IMG_H 512
#define PLANE (IMG_W * IMG_H)
#define RPT   8
#define STRIPS_PER_PLANE (IMG_H / RPT)   // 64

__device__ __forceinline__ float med3f(float a, float b, float c) {
    return fmaxf(fminf(a, b), fminf(fmaxf(a, b), c));
}

struct RawRow {
    float4 v;
    float l, r;
};

struct SortedRow {
    float lo0, lo1, lo2, lo3;
    float mi0, mi1, mi2, mi3;
    float hi0, hi1, hi2, hi3;
};

__device__ __forceinline__ RawRow load_raw(const float* __restrict__ ip,
                                           int y, int x0, int xl, int xr) {
    const float* __restrict__ rp = ip + y * IMG_W;
    RawRow o;
    o.v = *(const float4*)(rp + x0);
    o.l = rp[xl];
    o.r = rp[xr];
    return o;
}

__device__ __forceinline__ SortedRow sort_row(const RawRow& rr) {
    float s0 = rr.l, s1 = rr.v.x, s2 = rr.v.y, s3 = rr.v.z, s4 = rr.v.w, s5 = rr.r;
    SortedRow o;
    #define SORT3(a_, b_, c_, LO, MI, HI) {            \
        float a = (a_), b = (b_), c = (c_), t;          \
        t = fminf(a, b); b = fmaxf(a, b); a = t;        \
        t = fminf(b, c); c = fmaxf(b, c); b = t;        \
        t = fminf(a, b); b = fmaxf(a, b); a = t;        \
        o.LO = a; o.MI = b; o.HI = c; }
    SORT3(s0, s1, s2, lo0, mi0, hi0);
    SORT3(s1, s2, s3, lo1, mi1, hi1);
    SORT3(s2, s3, s4, lo2, mi2, hi2);
    SORT3(s3, s4, s5, lo3, mi3, hi3);
    #undef SORT3
    return o;
}

__device__ __forceinline__ float tail(float lA, float lB, float lC,
                                      float mA, float mB, float mC,
                                      float hA, float hB, float hC) {
    float mx = fmaxf(fmaxf(lA, lB), lC);
    float mn = fminf(fminf(hA, hB), hC);
    float md = med3f(mA, mB, mC);
    return med3f(mx, md, mn);
}

__global__ __launch_bounds__(256)
void MedianFilter2D_68745246540291_kernel(const float* __restrict__ in,
                                          float* __restrict__ out) {
    const int tid   = threadIdx.x;
    const int t128  = tid & 127;
    const int strip = blockIdx.x * 2 + (tid >> 7);

    const int plane = strip >> 6;                 // / STRIPS_PER_PLANE
    const int sy    = strip & (STRIPS_PER_PLANE - 1);
    const int y0    = sy * RPT;
    const int x0    = t128 * 4;

    const float* __restrict__ ip = in  + (size_t)plane * PLANE;
    float*       __restrict__ op = out + (size_t)plane * PLANE;

    const int xl = (t128 == 0)   ? 1         : x0 - 1;
    const int xr = (t128 == 127) ? IMG_W - 2 : x0 + 4;

    const int ytop = (sy == 0)                    ? 1         : y0 - 1;
    const int ybot = (sy == STRIPS_PER_PLANE - 1) ? IMG_H - 2 : y0 + RPT;

    // Depth-2 software pipeline: rows i+1 and i+2 in flight during compute of row i.
    SortedRow A = sort_row(load_raw(ip, ytop, x0, xl, xr));
    SortedRow B = sort_row(load_raw(ip, y0,   x0, xl, xr));
    RawRow n1 = load_raw(ip, y0 + 1, x0, xl, xr);
    RawRow n2 = load_raw(ip, y0 + 2, x0, xl, xr);

    #pragma unroll
    for (int i = 0; i < RPT; i++) {
        RawRow cur = n1;
        n1 = n2;
        if (i + 2 < RPT) {
            const int yn = (i + 3 == RPT) ? ybot : (y0 + i + 3);
            n2 = load_raw(ip, yn, x0, xl, xr);
        }

        SortedRow C = sort_row(cur);

        float4 res;
        res.x = tail(A.lo0, B.lo0, C.lo0, A.mi0, B.mi0, C.mi0, A.hi0, B.hi0, C.hi0);
        res.y = tail(A.lo1, B.lo1, C.lo1, A.mi1, B.mi1, C.mi1, A.hi1, B.hi1, C.hi1);
        res.z = tail(A.lo2, B.lo2, C.lo2, A.mi2, B.mi2, C.mi2, A.hi2, B.hi2, C.hi2);
        res.w = tail(A.lo3, B.lo3, C.lo3, A.mi3, B.mi3, C.mi3, A.hi3, B.hi3, C.hi3);

        *(float4*)(op + (size_t)(y0 + i) * IMG_W + x0) = res;

        A = B; B = C;   // register renaming under full unroll
    }
}

extern "C" void kernel_launch(void* const* d_in, const int* in_sizes, int n_in,
                              void* d_out, int out_size) {
    const float* image = (const float*)d_in[0];
    float* out = (float*)d_out;

    // 48 planes * 64 strips(8 rows); 2 strips per 256-thread block -> 1536 blocks
    dim3 block(256, 1, 1);
    dim3 grid(48 * STRIPS_PER_PLANE / 2, 1, 1);
    MedianFilter2D_68745246540291_kernel<<<grid, block>>>(image, out);
}

// round 8
// speedup vs baseline: 1.1078x; 1.0113x over previous
#include <cuda_runtime.h>

#define IMG_W 512
#define IMG_H 512
#define PLANE (IMG_W * IMG_H)
#define RPT   8
#define STRIPS_PER_PLANE (IMG_H / RPT)   // 64
#define CPT   8                           // columns per thread
#define TPS   (IMG_W / CPT)               // 64 threads per strip row

__device__ __forceinline__ float med3f(float a, float b, float c) {
    return fmaxf(fminf(a, b), fminf(fmaxf(a, b), c));
}

struct RawRow {           // 10 values: halo-left, 8 cols, halo-right
    float4 a, b;
    float l, r;
};

struct SortedRow {        // horizontal sorted triples for 8 output columns
    float lo[CPT], mi[CPT], hi[CPT];
};

__device__ __forceinline__ RawRow load_raw(const float* __restrict__ ip,
                                           int y, int x0, int xl, int xr) {
    const float* __restrict__ rp = ip + y * IMG_W;
    RawRow o;
    o.a = *(const float4*)(rp + x0);
    o.b = *(const float4*)(rp + x0 + 4);
    o.l = rp[xl];
    o.r = rp[xr];
    return o;
}

__device__ __forceinline__ SortedRow sort_row(const RawRow& rr) {
    float s[CPT + 2];
    s[0] = rr.l;
    s[1] = rr.a.x; s[2] = rr.a.y; s[3] = rr.a.z; s[4] = rr.a.w;
    s[5] = rr.b.x; s[6] = rr.b.y; s[7] = rr.b.z; s[8] = rr.b.w;
    s[9] = rr.r;
    SortedRow o;
    #pragma unroll
    for (int j = 0; j < CPT; j++) {
        float a = s[j], b = s[j + 1], c = s[j + 2], t;
        t = fminf(a, b); b = fmaxf(a, b); a = t;
        t = fminf(b, c); c = fmaxf(b, c); b = t;
        t = fminf(a, b); b = fmaxf(a, b); a = t;
        o.lo[j] = a; o.mi[j] = b; o.hi[j] = c;
    }
    return o;
}

__device__ __forceinline__ float tail(float lA, float lB, float lC,
                                      float mA, float mB, float mC,
                                      float hA, float hB, float hC) {
    float mx = fmaxf(fmaxf(lA, lB), lC);   // max of mins
    float mn = fminf(fminf(hA, hB), hC);   // min of maxes
    float md = med3f(mA, mB, mC);          // med of mids
    return med3f(mx, md, mn);
}

__global__ __launch_bounds__(128)
void MedianFilter2D_68745246540291_kernel(const float* __restrict__ in,
                                          float* __restrict__ out) {
    const int tid   = threadIdx.x;
    const int t64   = tid & (TPS - 1);
    const int strip = blockIdx.x * 2 + (tid >> 6);

    const int plane = strip >> 6;                 // / STRIPS_PER_PLANE
    const int sy    = strip & (STRIPS_PER_PLANE - 1);
    const int y0    = sy * RPT;
    const int x0    = t64 * CPT;

    const float* __restrict__ ip = in  + (size_t)plane * PLANE;
    float*       __restrict__ op = out + (size_t)plane * PLANE;

    const int xl = (t64 == 0)       ? 1         : x0 - 1;
    const int xr = (t64 == TPS - 1) ? IMG_W - 2 : x0 + CPT;

    const int ytop = (sy == 0)                    ? 1         : y0 - 1;
    const int ybot = (sy == STRIPS_PER_PLANE - 1) ? IMG_H - 2 : y0 + RPT;

    SortedRow A = sort_row(load_raw(ip, ytop, x0, xl, xr));
    SortedRow B = sort_row(load_raw(ip, y0,   x0, xl, xr));
    RawRow nxt  = load_raw(ip, y0 + 1, x0, xl, xr);

    #pragma unroll
    for (int i = 0; i < RPT; i++) {
        RawRow cur = nxt;
        if (i + 1 < RPT) {
            const int yn = (i + 2 == RPT) ? ybot : (y0 + i + 2);
            nxt = load_raw(ip, yn, x0, xl, xr);
        }

        SortedRow C = sort_row(cur);

        float4 r0, r1;
        r0.x = tail(A.lo[0], B.lo[0], C.lo[0], A.mi[0], B.mi[0], C.mi[0], A.hi[0], B.hi[0], C.hi[0]);
        r0.y = tail(A.lo[1], B.lo[1], C.lo[1], A.mi[1], B.mi[1], C.mi[1], A.hi[1], B.hi[1], C.hi[1]);
        r0.z = tail(A.lo[2], B.lo[2], C.lo[2], A.mi[2], B.mi[2], C.mi[2], A.hi[2], B.hi[2], C.hi[2]);
        r0.w = tail(A.lo[3], B.lo[3], C.lo[3], A.mi[3], B.mi[3], C.mi[3], A.hi[3], B.hi[3], C.hi[3]);
        r1.x = tail(A.lo[4], B.lo[4], C.lo[4], A.mi[4], B.mi[4], C.mi[4], A.hi[4], B.hi[4], C.hi[4]);
        r1.y = tail(A.lo[5], B.lo[5], C.lo[5], A.mi[5], B.mi[5], C.mi[5], A.hi[5], B.hi[5], C.hi[5]);
        r1.z = tail(A.lo[6], B.lo[6], C.lo[6], A.mi[6], B.mi[6], C.mi[6], A.hi[6], B.hi[6], C.hi[6]);
        r1.w = tail(A.lo[7], B.lo[7], C.lo[7], A.mi[7], B.mi[7], C.mi[7], A.hi[7], B.hi[7], C.hi[7]);

        float* orow = op + (size_t)(y0 + i) * IMG_W + x0;
        *(float4*)(orow)     = r0;
        *(float4*)(orow + 4) = r1;

        A = B; B = C;   // register renaming under full unroll
    }
}

extern "C" void kernel_launch(void* const* d_in, const int* in_sizes, int n_in,
                              void* d_out, int out_size) {
    const float* image = (const float*)d_in[0];
    float* out = (float*)d_out;

    // 48 planes * 64 strips; 2 strips per 128-thread block -> 1536 blocks
    dim3 block(128, 1, 1);
    dim3 grid(48 * STRIPS_PER_PLANE / 2, 1, 1);
    MedianFilter2D_68745246540291_kernel<<<grid, block>>>(image, out);
}